// round 2
// baseline (speedup 1.0000x reference)
#include <cuda_runtime.h>
#include <cuda_bf16.h>
#include <stdint.h>

#define NN 100000
#define EE 1600000
#define FN 32
#define FE 8
#define HH 64

// ---------------- scratch (device globals; no allocation allowed) -------------
__device__ float g_g[NN * HH];    // per-node transformed features (g1 / g2)
__device__ float g_acc[NN * HH];  // scatter accumulator (conv1 then conv2)
__device__ float g_a[NN * HH];    // h2 @ W_p1[0:64]
__device__ float g_b[NN * HH];    // h2 @ W_p1[64:128]
__device__ float g_deg[NN];
__device__ float g_dinv[NN];

// ---------------- degree / norm ----------------
__global__ void k_deg_init() {
    int n = blockIdx.x * blockDim.x + threadIdx.x;
    if (n < NN) g_deg[n] = 1.0f;  // self loop
}

__global__ void k_deg(const int* __restrict__ ei) {
    int e = blockIdx.x * blockDim.x + threadIdx.x;
    if (e < EE) {
        int d = __ldg(&ei[EE + e]);
        atomicAdd(&g_deg[d], 1.0f);
    }
}

__global__ void k_dinv() {
    int n = blockIdx.x * blockDim.x + threadIdx.x;
    if (n < NN) g_dinv[n] = rsqrtf(g_deg[n]);
}

// ---------------- K1: h0 = relu(x@We+be); g1 = h0@Wc1; acc = g1*dinv^2 -------
// block (64, 4): 4 nodes per block, 64 output features per node. N % 4 == 0.
__global__ void k_embed(const float* __restrict__ x,
                        const float* __restrict__ We,
                        const float* __restrict__ be,
                        const float* __restrict__ Wc1) {
    const int j = threadIdx.x;        // output feature 0..63
    const int y = threadIdx.y;        // node slot 0..3
    const int node = blockIdx.x * 4 + y;

    __shared__ float xs[4][FN];
    __shared__ float ts[4][HH];

    // coalesced load of 4 x-rows (128 floats) by first 128 threads
    int t = y * 64 + j;
    if (t < 4 * FN) {
        int nn = blockIdx.x * 4 + t / FN;
        xs[t / FN][t % FN] = x[(long)nn * FN + (t % FN)];
    }
    __syncthreads();

    float tv = __ldg(&be[j]);
#pragma unroll
    for (int k = 0; k < FN; k++) tv = fmaf(xs[y][k], __ldg(&We[k * HH + j]), tv);
    tv = fmaxf(tv, 0.0f);
    ts[y][j] = tv;
    __syncthreads();

    float g = 0.0f;
#pragma unroll
    for (int m = 0; m < HH; m++) g = fmaf(ts[y][m], __ldg(&Wc1[m * HH + j]), g);

    float di = g_dinv[node];
    g_g[(long)node * HH + j] = g;
    g_acc[(long)node * HH + j] = g * di * di;  // self-loop message
}

// ---------------- scatter: acc[dst] += g[src] * dinv[src]*dinv[dst] ----------
// 16 threads per edge, float4 per thread, red.global.add.v4.f32
__global__ void k_scatter(const int* __restrict__ ei) {
    long long gid = (long long)blockIdx.x * blockDim.x + threadIdx.x;
    int e = (int)(gid >> 4);
    if (e >= EE) return;
    int p = (int)(gid & 15);

    int s = __ldg(&ei[e]);
    int d = __ldg(&ei[EE + e]);
    float nrm = g_dinv[s] * g_dinv[d];

    const float4* sp = reinterpret_cast<const float4*>(&g_g[(long)s * HH]) + p;
    float4 v = __ldg(sp);
    v.x *= nrm; v.y *= nrm; v.z *= nrm; v.w *= nrm;

    float* dp = &g_acc[(long)d * HH + p * 4];
    asm volatile("red.global.add.v4.f32 [%0], {%1,%2,%3,%4};"
                 :: "l"(dp), "f"(v.x), "f"(v.y), "f"(v.z), "f"(v.w)
                 : "memory");
}

// ---------------- K3: h1 = relu(acc+bc1); g2 = h1@Wc2; acc = g2*dinv^2 -------
__global__ void k_mid(const float* __restrict__ bc,
                      const float* __restrict__ Wc) {
    const int j = threadIdx.x;
    const int y = threadIdx.y;
    const int node = blockIdx.x * 4 + y;

    __shared__ float hs[4][HH];

    float h = fmaxf(g_acc[(long)node * HH + j] + __ldg(&bc[j]), 0.0f);
    hs[y][j] = h;
    __syncthreads();

    float g = 0.0f;
#pragma unroll
    for (int m = 0; m < HH; m++) g = fmaf(hs[y][m], __ldg(&Wc[m * HH + j]), g);

    float di = g_dinv[node];
    g_g[(long)node * HH + j] = g;
    g_acc[(long)node * HH + j] = g * di * di;
}

// ---------------- K5: h2 = relu(acc+bc2); a = h2@Wp1[0:64]; b = h2@Wp1[64:128]
__global__ void k_node_final(const float* __restrict__ bc2,
                             const float* __restrict__ Wp1) {
    const int j = threadIdx.x;
    const int y = threadIdx.y;
    const int node = blockIdx.x * 4 + y;

    __shared__ float hs[4][HH];

    float h = fmaxf(g_acc[(long)node * HH + j] + __ldg(&bc2[j]), 0.0f);
    hs[y][j] = h;
    __syncthreads();

    float av = 0.0f, bv = 0.0f;
#pragma unroll
    for (int m = 0; m < HH; m++) {
        float hm = hs[y][m];
        av = fmaf(hm, __ldg(&Wp1[m * HH + j]), av);
        bv = fmaf(hm, __ldg(&Wp1[(HH + m) * HH + j]), bv);
    }
    g_a[(long)node * HH + j] = av;
    g_b[(long)node * HH + j] = bv;
}

// ---------------- K6: per-edge output ----------------------------------------
// out[e] = (relu(a[src] + b[dst] + edge_attr[e]@Wp1[128:136] + bp1)) . wp2 + bp2
// 16 threads per edge, each handles 4 of 64 z components.
__global__ void k_edge_out(const int* __restrict__ ei,
                           const float* __restrict__ eattr,
                           const float* __restrict__ Wp1,
                           const float* __restrict__ bp1,
                           const float* __restrict__ wp2,
                           const float* __restrict__ bp2,
                           float* __restrict__ out) {
    long long gid = (long long)blockIdx.x * blockDim.x + threadIdx.x;
    int e = (int)(gid >> 4);
    if (e >= EE) return;
    int p = (int)(gid & 15);
    int j0 = p * 4;

    int s = __ldg(&ei[e]);
    int d = __ldg(&ei[EE + e]);

    // edge attrs: lanes 0..7 of each 16-group load one value, broadcast by shfl
    float eav = (p < FE) ? __ldg(&eattr[(long)e * FE + p]) : 0.0f;

    float4 av = __ldg(reinterpret_cast<const float4*>(&g_a[(long)s * HH]) + p);
    float4 bv = __ldg(reinterpret_cast<const float4*>(&g_b[(long)d * HH]) + p);

    float4 c = __ldg(reinterpret_cast<const float4*>(bp1) + p);
#pragma unroll
    for (int k = 0; k < FE; k++) {
        float ek = __shfl_sync(0xffffffffu, eav, k, 16);
        float4 w = __ldg(reinterpret_cast<const float4*>(&Wp1[(128 + k) * HH + j0]));
        c.x = fmaf(ek, w.x, c.x);
        c.y = fmaf(ek, w.y, c.y);
        c.z = fmaf(ek, w.z, c.z);
        c.w = fmaf(ek, w.w, c.w);
    }

    float4 z;
    z.x = fmaxf(av.x + bv.x + c.x, 0.0f);
    z.y = fmaxf(av.y + bv.y + c.y, 0.0f);
    z.z = fmaxf(av.z + bv.z + c.z, 0.0f);
    z.w = fmaxf(av.w + bv.w + c.w, 0.0f);

    float4 w2 = __ldg(reinterpret_cast<const float4*>(wp2) + p);
    float part = z.x * w2.x + z.y * w2.y + z.z * w2.z + z.w * w2.w;

#pragma unroll
    for (int off = 8; off >= 1; off >>= 1)
        part += __shfl_down_sync(0xffffffffu, part, off, 16);

    if (p == 0) out[e] = part + __ldg(bp2);
}

// ---------------- host launcher ----------------------------------------------
extern "C" void kernel_launch(void* const* d_in, const int* in_sizes, int n_in,
                              void* d_out, int out_size) {
    // metadata order: x, edge_attr, W_embed, b_embed, W_c1, b_c1, W_c2, b_c2,
    //                 W_p1, b_p1, W_p2, b_p2, edge_index
    const float* x       = (const float*)d_in[0];
    const float* eattr   = (const float*)d_in[1];
    const float* We      = (const float*)d_in[2];
    const float* be      = (const float*)d_in[3];
    const float* Wc1     = (const float*)d_in[4];
    const float* bc1     = (const float*)d_in[5];
    const float* Wc2     = (const float*)d_in[6];
    const float* bc2     = (const float*)d_in[7];
    const float* Wp1     = (const float*)d_in[8];
    const float* bp1     = (const float*)d_in[9];
    const float* wp2     = (const float*)d_in[10];
    const float* bp2     = (const float*)d_in[11];
    const int*   ei      = (const int*)d_in[12];   // int32 (JAX x64 disabled)
    float* out = (float*)d_out;

    // degrees + norm
    k_deg_init<<<(NN + 255) / 256, 256>>>();
    k_deg<<<(EE + 255) / 256, 256>>>(ei);
    k_dinv<<<(NN + 255) / 256, 256>>>();

    dim3 nb(64, 4);
    int ngrid = NN / 4;  // N divisible by 4

    // embed + conv1 transform
    k_embed<<<ngrid, nb>>>(x, We, be, Wc1);

    // conv1 scatter
    long long st = (long long)EE * 16;
    int sgrid = (int)((st + 255) / 256);
    k_scatter<<<sgrid, 256>>>(ei);

    // conv1 epilogue + conv2 transform
    k_mid<<<ngrid, nb>>>(bc1, Wc2);

    // conv2 scatter
    k_scatter<<<sgrid, 256>>>(ei);

    // conv2 epilogue + edge-MLP node-side precompute
    k_node_final<<<ngrid, nb>>>(bc2, Wp1);

    // per-edge output
    k_edge_out<<<sgrid, 256>>>(ei, eattr, Wp1, bp1, wp2, bp2, out);
}

// round 3
// speedup vs baseline: 1.1074x; 1.1074x over previous
#include <cuda_runtime.h>
#include <cuda_bf16.h>
#include <stdint.h>

#define NN 100000
#define EE 1600000
#define FN 32
#define FE 8
#define HH 64
#define NPB 16   // nodes per block in node-level kernels (NN % NPB == 0)

// ---------------- scratch (device globals) ------------------------------------
__device__ float g_g[NN * HH];    // g' = (h@W) * dinv   (conv1 then conv2)
__device__ float g_acc[NN * HH];  // scatter accumulator
__device__ float g_a[NN * HH];    // h2 @ W_p1[0:64]
__device__ float g_b[NN * HH];    // h2 @ W_p1[64:128]
__device__ float g_deg[NN];
__device__ float g_dinv[NN];

// ---------------- degree / norm ----------------
__global__ void k_deg_init() {
    int n = blockIdx.x * blockDim.x + threadIdx.x;
    if (n < NN) g_deg[n] = 1.0f;  // self loop
}

__global__ void k_deg(const int* __restrict__ ei) {
    int e = blockIdx.x * blockDim.x + threadIdx.x;
    if (e < EE) atomicAdd(&g_deg[__ldg(&ei[EE + e])], 1.0f);
}

__global__ void k_dinv() {
    int n = blockIdx.x * blockDim.x + threadIdx.x;
    if (n < NN) g_dinv[n] = rsqrtf(g_deg[n]);
}

// ---------------- K1: h0 = relu(x@We+be); g1' = (h0@Wc1)*dinv ----------------
// 256 threads = 64 j-lanes x 4 slots; each slot handles 4 nodes (16 nodes/blk).
__global__ __launch_bounds__(256) void k_embed(const float* __restrict__ x,
                                               const float* __restrict__ We,
                                               const float* __restrict__ be,
                                               const float* __restrict__ Wc1) {
    const int tid = threadIdx.x;
    const int j = tid & 63;
    const int y = tid >> 6;            // 0..3
    const int base = blockIdx.x * NPB;

    __shared__ float sWe[FN * HH];     // 8 KB
    __shared__ float sWc[HH * HH];     // 16 KB
    __shared__ float xs[NPB * FN];     // 2 KB
    __shared__ float hs[NPB * HH];     // 4 KB

    for (int i = tid; i < FN * HH; i += 256) sWe[i] = We[i];
    for (int i = tid; i < HH * HH; i += 256) sWc[i] = Wc1[i];
    for (int i = tid; i < NPB * FN; i += 256) xs[i] = x[(long)base * FN + i];
    __syncthreads();

    // stage 1: h0 rows for my 4 nodes
    const float bj = __ldg(&be[j]);
    float h[4] = {bj, bj, bj, bj};
#pragma unroll
    for (int m = 0; m < FN; m++) {
        float w = sWe[m * HH + j];
#pragma unroll
        for (int r = 0; r < 4; r++)
            h[r] = fmaf(xs[(y * 4 + r) * FN + m], w, h[r]);
    }
#pragma unroll
    for (int r = 0; r < 4; r++)
        hs[(y * 4 + r) * HH + j] = fmaxf(h[r], 0.0f);
    __syncthreads();

    // stage 2: g1 = h0 @ Wc1
    float g[4] = {0.f, 0.f, 0.f, 0.f};
#pragma unroll
    for (int m = 0; m < HH; m++) {
        float w = sWc[m * HH + j];
#pragma unroll
        for (int r = 0; r < 4; r++)
            g[r] = fmaf(hs[(y * 4 + r) * HH + m], w, g[r]);
    }
#pragma unroll
    for (int r = 0; r < 4; r++) {
        int node = base + y * 4 + r;
        float gp = g[r] * g_dinv[node];   // g' = g * dinv
        g_g[(long)node * HH + j] = gp;
        g_acc[(long)node * HH + j] = gp;  // self-loop seed
    }
}

// ---------------- scatter: acc[dst] += g'[src] --------------------------------
// 16 threads per edge, float4 per thread, red.global.add.v4.f32
__global__ __launch_bounds__(256) void k_scatter(const int* __restrict__ ei) {
    long long gid = (long long)blockIdx.x * blockDim.x + threadIdx.x;
    int e = (int)(gid >> 4);
    if (e >= EE) return;
    int p = (int)(gid & 15);

    int s = __ldg(&ei[e]);
    int d = __ldg(&ei[EE + e]);

    float4 v = __ldg(reinterpret_cast<const float4*>(&g_g[(long)s * HH]) + p);
    float* dp = &g_acc[(long)d * HH + p * 4];
    asm volatile("red.global.add.v4.f32 [%0], {%1,%2,%3,%4};"
                 :: "l"(dp), "f"(v.x), "f"(v.y), "f"(v.z), "f"(v.w)
                 : "memory");
}

// ---------------- K3: h1 = relu(acc*dinv + bc1); g2' = (h1@Wc2)*dinv ---------
__global__ __launch_bounds__(256) void k_mid(const float* __restrict__ bc,
                                             const float* __restrict__ Wc) {
    const int tid = threadIdx.x;
    const int j = tid & 63;
    const int y = tid >> 6;
    const int base = blockIdx.x * NPB;

    __shared__ float sWc[HH * HH];     // 16 KB
    __shared__ float hs[NPB * HH];     // 4 KB

    for (int i = tid; i < HH * HH; i += 256) sWc[i] = Wc[i];
    for (int i = tid; i < NPB * HH; i += 256) {
        int node = base + (i >> 6);
        hs[i] = fmaxf(g_acc[(long)base * HH + i] * g_dinv[node] + __ldg(&bc[i & 63]), 0.0f);
    }
    __syncthreads();

    float g[4] = {0.f, 0.f, 0.f, 0.f};
#pragma unroll
    for (int m = 0; m < HH; m++) {
        float w = sWc[m * HH + j];
#pragma unroll
        for (int r = 0; r < 4; r++)
            g[r] = fmaf(hs[(y * 4 + r) * HH + m], w, g[r]);
    }
#pragma unroll
    for (int r = 0; r < 4; r++) {
        int node = base + y * 4 + r;
        float gp = g[r] * g_dinv[node];
        g_g[(long)node * HH + j] = gp;
        g_acc[(long)node * HH + j] = gp;
    }
}

// ---------------- K5: h2 = relu(acc*dinv + bc2); a,b = h2 @ Wp1[0:128] -------
__global__ __launch_bounds__(256) void k_node_final(const float* __restrict__ bc2,
                                                    const float* __restrict__ Wp1) {
    const int tid = threadIdx.x;
    const int j = tid & 63;
    const int y = tid >> 6;
    const int base = blockIdx.x * NPB;

    __shared__ float sWa[HH * HH];     // 16 KB
    __shared__ float sWb[HH * HH];     // 16 KB
    __shared__ float hs[NPB * HH];     // 4 KB

    for (int i = tid; i < HH * HH; i += 256) {
        sWa[i] = Wp1[i];
        sWb[i] = Wp1[HH * HH + i];
    }
    for (int i = tid; i < NPB * HH; i += 256) {
        int node = base + (i >> 6);
        hs[i] = fmaxf(g_acc[(long)base * HH + i] * g_dinv[node] + __ldg(&bc2[i & 63]), 0.0f);
    }
    __syncthreads();

    float a[4] = {0.f, 0.f, 0.f, 0.f};
    float b[4] = {0.f, 0.f, 0.f, 0.f};
#pragma unroll
    for (int m = 0; m < HH; m++) {
        float wa = sWa[m * HH + j];
        float wb = sWb[m * HH + j];
#pragma unroll
        for (int r = 0; r < 4; r++) {
            float hm = hs[(y * 4 + r) * HH + m];
            a[r] = fmaf(hm, wa, a[r]);
            b[r] = fmaf(hm, wb, b[r]);
        }
    }
#pragma unroll
    for (int r = 0; r < 4; r++) {
        int node = base + y * 4 + r;
        g_a[(long)node * HH + j] = a[r];
        g_b[(long)node * HH + j] = b[r];
    }
}

// ---------------- K6: per-edge output ----------------------------------------
__global__ __launch_bounds__(256) void k_edge_out(const int* __restrict__ ei,
                           const float* __restrict__ eattr,
                           const float* __restrict__ Wp1,
                           const float* __restrict__ bp1,
                           const float* __restrict__ wp2,
                           const float* __restrict__ bp2,
                           float* __restrict__ out) {
    long long gid = (long long)blockIdx.x * blockDim.x + threadIdx.x;
    int e = (int)(gid >> 4);
    if (e >= EE) return;
    int p = (int)(gid & 15);
    int j0 = p * 4;

    int s = __ldg(&ei[e]);
    int d = __ldg(&ei[EE + e]);

    float eav = (p < FE) ? __ldg(&eattr[(long)e * FE + p]) : 0.0f;

    float4 av = __ldg(reinterpret_cast<const float4*>(&g_a[(long)s * HH]) + p);
    float4 bv = __ldg(reinterpret_cast<const float4*>(&g_b[(long)d * HH]) + p);

    float4 c = __ldg(reinterpret_cast<const float4*>(bp1) + p);
#pragma unroll
    for (int k = 0; k < FE; k++) {
        float ek = __shfl_sync(0xffffffffu, eav, k, 16);
        float4 w = __ldg(reinterpret_cast<const float4*>(&Wp1[(128 + k) * HH + j0]));
        c.x = fmaf(ek, w.x, c.x);
        c.y = fmaf(ek, w.y, c.y);
        c.z = fmaf(ek, w.z, c.z);
        c.w = fmaf(ek, w.w, c.w);
    }

    float4 z;
    z.x = fmaxf(av.x + bv.x + c.x, 0.0f);
    z.y = fmaxf(av.y + bv.y + c.y, 0.0f);
    z.z = fmaxf(av.z + bv.z + c.z, 0.0f);
    z.w = fmaxf(av.w + bv.w + c.w, 0.0f);

    float4 w2 = __ldg(reinterpret_cast<const float4*>(wp2) + p);
    float part = z.x * w2.x + z.y * w2.y + z.z * w2.z + z.w * w2.w;

#pragma unroll
    for (int off = 8; off >= 1; off >>= 1)
        part += __shfl_down_sync(0xffffffffu, part, off, 16);

    if (p == 0) out[e] = part + __ldg(bp2);
}

// ---------------- host launcher ----------------------------------------------
extern "C" void kernel_launch(void* const* d_in, const int* in_sizes, int n_in,
                              void* d_out, int out_size) {
    const float* x       = (const float*)d_in[0];
    const float* eattr   = (const float*)d_in[1];
    const float* We      = (const float*)d_in[2];
    const float* be      = (const float*)d_in[3];
    const float* Wc1     = (const float*)d_in[4];
    const float* bc1     = (const float*)d_in[5];
    const float* Wc2     = (const float*)d_in[6];
    const float* bc2     = (const float*)d_in[7];
    const float* Wp1     = (const float*)d_in[8];
    const float* bp1     = (const float*)d_in[9];
    const float* wp2     = (const float*)d_in[10];
    const float* bp2     = (const float*)d_in[11];
    const int*   ei      = (const int*)d_in[12];
    float* out = (float*)d_out;

    k_deg_init<<<(NN + 255) / 256, 256>>>();
    k_deg<<<(EE + 255) / 256, 256>>>(ei);
    k_dinv<<<(NN + 255) / 256, 256>>>();

    int ngrid = NN / NPB;  // 6250

    k_embed<<<ngrid, 256>>>(x, We, be, Wc1);

    long long st = (long long)EE * 16;
    int sgrid = (int)((st + 255) / 256);
    k_scatter<<<sgrid, 256>>>(ei);

    k_mid<<<ngrid, 256>>>(bc1, Wc2);

    k_scatter<<<sgrid, 256>>>(ei);

    k_node_final<<<ngrid, 256>>>(bc2, Wp1);

    k_edge_out<<<sgrid, 256>>>(ei, eattr, Wp1, bp1, wp2, bp2, out);
}

// round 4
// speedup vs baseline: 1.2926x; 1.1673x over previous
#include <cuda_runtime.h>
#include <cuda_bf16.h>
#include <stdint.h>

#define NN 100000
#define EE 1600000
#define FN 32
#define FE 8
#define HH 64
#define NPB 32   // nodes per block (100000 / 32 = 3125 exactly)

// ---------------- scratch (device globals) ------------------------------------
__device__ float g_g[NN * HH];    // g' = (h@W) * dinv   (conv1 then conv2)
__device__ float g_acc[NN * HH];  // scatter accumulator
__device__ float g_a[NN * HH];    // h2 @ W_p1[0:64]
__device__ float g_b[NN * HH];    // h2 @ W_p1[64:128]
__device__ float g_deg[NN];
__device__ float g_dinv[NN];

// ---------------- degree / norm ----------------
__global__ void k_deg_init() {
    int n = blockIdx.x * blockDim.x + threadIdx.x;
    if (n < NN) g_deg[n] = 1.0f;  // self loop
}

__global__ void k_deg(const int* __restrict__ ei) {
    int e = blockIdx.x * blockDim.x + threadIdx.x;
    if (e < EE) atomicAdd(&g_deg[__ldg(&ei[EE + e])], 1.0f);
}

__global__ void k_dinv() {
    int n = blockIdx.x * blockDim.x + threadIdx.x;
    if (n < NN) g_dinv[n] = rsqrtf(g_deg[n]);
}

// float4 helpers
__device__ __forceinline__ void cp4(float* dst, const float* src, int nfl, int tid) {
    const float4* s = (const float4*)src;
    float4* d = (float4*)dst;
    for (int i = tid; i < nfl / 4; i += 256) d[i] = s[i];
}

// ---------------- K1: h0 = relu(x@We+be); g1' = (h0@Wc1)*dinv ----------------
// 256 threads: jg = tid&15 (4 features each), ys = tid>>4 (2 nodes each).
__global__ __launch_bounds__(256) void k_embed(const float* __restrict__ x,
                                               const float* __restrict__ We,
                                               const float* __restrict__ be,
                                               const float* __restrict__ Wc1) {
    const int tid = threadIdx.x;
    const int jg = tid & 15;
    const int j0 = jg * 4;
    const int ys = tid >> 4;           // 0..15
    const int n0 = ys * 2;
    const int base = blockIdx.x * NPB;

    __shared__ float sWe[FN * HH];     // 8 KB
    __shared__ float sWc[HH * HH];     // 16 KB
    __shared__ float xs[NPB * FN];     // 4 KB
    __shared__ float hs[NPB * HH];     // 8 KB

    cp4(sWe, We, FN * HH, tid);
    cp4(sWc, Wc1, HH * HH, tid);
    cp4(xs, x + (long)base * FN, NPB * FN, tid);
    __syncthreads();

    // stage 1: h0 = relu(x @ We + be) for 2 nodes x 4 features
    float a0[4] = {0.f, 0.f, 0.f, 0.f};
    float a1[4] = {0.f, 0.f, 0.f, 0.f};
#pragma unroll
    for (int mg = 0; mg < FN / 4; mg++) {
        float4 v0 = *(const float4*)&xs[n0 * FN + mg * 4];
        float4 v1 = *(const float4*)&xs[(n0 + 1) * FN + mg * 4];
        const float* p0 = (const float*)&v0;
        const float* p1 = (const float*)&v1;
#pragma unroll
        for (int mm = 0; mm < 4; mm++) {
            float4 w = *(const float4*)&sWe[(mg * 4 + mm) * HH + j0];
            float x0 = p0[mm], x1 = p1[mm];
            a0[0] = fmaf(x0, w.x, a0[0]); a0[1] = fmaf(x0, w.y, a0[1]);
            a0[2] = fmaf(x0, w.z, a0[2]); a0[3] = fmaf(x0, w.w, a0[3]);
            a1[0] = fmaf(x1, w.x, a1[0]); a1[1] = fmaf(x1, w.y, a1[1]);
            a1[2] = fmaf(x1, w.z, a1[2]); a1[3] = fmaf(x1, w.w, a1[3]);
        }
    }
    {
        float4 bb = *(const float4*)&be[j0];
        float4 h0, h1;
        h0.x = fmaxf(a0[0] + bb.x, 0.f); h0.y = fmaxf(a0[1] + bb.y, 0.f);
        h0.z = fmaxf(a0[2] + bb.z, 0.f); h0.w = fmaxf(a0[3] + bb.w, 0.f);
        h1.x = fmaxf(a1[0] + bb.x, 0.f); h1.y = fmaxf(a1[1] + bb.y, 0.f);
        h1.z = fmaxf(a1[2] + bb.z, 0.f); h1.w = fmaxf(a1[3] + bb.w, 0.f);
        *(float4*)&hs[n0 * HH + j0] = h0;
        *(float4*)&hs[(n0 + 1) * HH + j0] = h1;
    }
    __syncthreads();

    // stage 2: g1 = h0 @ Wc1
    float g0[4] = {0.f, 0.f, 0.f, 0.f};
    float g1[4] = {0.f, 0.f, 0.f, 0.f};
#pragma unroll
    for (int mg = 0; mg < HH / 4; mg++) {
        float4 v0 = *(const float4*)&hs[n0 * HH + mg * 4];
        float4 v1 = *(const float4*)&hs[(n0 + 1) * HH + mg * 4];
        const float* p0 = (const float*)&v0;
        const float* p1 = (const float*)&v1;
#pragma unroll
        for (int mm = 0; mm < 4; mm++) {
            float4 w = *(const float4*)&sWc[(mg * 4 + mm) * HH + j0];
            float x0 = p0[mm], x1 = p1[mm];
            g0[0] = fmaf(x0, w.x, g0[0]); g0[1] = fmaf(x0, w.y, g0[1]);
            g0[2] = fmaf(x0, w.z, g0[2]); g0[3] = fmaf(x0, w.w, g0[3]);
            g1[0] = fmaf(x1, w.x, g1[0]); g1[1] = fmaf(x1, w.y, g1[1]);
            g1[2] = fmaf(x1, w.z, g1[2]); g1[3] = fmaf(x1, w.w, g1[3]);
        }
    }
    {
        float d0 = g_dinv[base + n0];
        float d1 = g_dinv[base + n0 + 1];
        float4 o0 = make_float4(g0[0] * d0, g0[1] * d0, g0[2] * d0, g0[3] * d0);
        float4 o1 = make_float4(g1[0] * d1, g1[1] * d1, g1[2] * d1, g1[3] * d1);
        long r0 = (long)(base + n0) * HH + j0;
        long r1 = (long)(base + n0 + 1) * HH + j0;
        *(float4*)&g_g[r0] = o0;  *(float4*)&g_acc[r0] = o0;
        *(float4*)&g_g[r1] = o1;  *(float4*)&g_acc[r1] = o1;
    }
}

// ---------------- scatter: acc[dst] += g'[src] --------------------------------
__global__ __launch_bounds__(256) void k_scatter(const int* __restrict__ ei) {
    long long gid = (long long)blockIdx.x * blockDim.x + threadIdx.x;
    int e = (int)(gid >> 4);
    if (e >= EE) return;
    int p = (int)(gid & 15);

    int s = __ldg(&ei[e]);
    int d = __ldg(&ei[EE + e]);

    float4 v = __ldg(reinterpret_cast<const float4*>(&g_g[(long)s * HH]) + p);
    float* dp = &g_acc[(long)d * HH + p * 4];
    asm volatile("red.global.add.v4.f32 [%0], {%1,%2,%3,%4};"
                 :: "l"(dp), "f"(v.x), "f"(v.y), "f"(v.z), "f"(v.w)
                 : "memory");
}

// ---------------- K3: h1 = relu(acc*dinv + bc1); g2' = (h1@Wc2)*dinv ---------
__global__ __launch_bounds__(256) void k_mid(const float* __restrict__ bc,
                                             const float* __restrict__ Wc) {
    const int tid = threadIdx.x;
    const int jg = tid & 15;
    const int j0 = jg * 4;
    const int ys = tid >> 4;
    const int n0 = ys * 2;
    const int base = blockIdx.x * NPB;

    __shared__ float sWc[HH * HH];     // 16 KB
    __shared__ float hs[NPB * HH];     // 8 KB

    cp4(sWc, Wc, HH * HH, tid);
    {
        const float4* acc4 = (const float4*)&g_acc[(long)base * HH];
        const float4* bc4 = (const float4*)bc;
        float4* hs4 = (float4*)hs;
        for (int i = tid; i < NPB * HH / 4; i += 256) {
            int row = i >> 4;                 // 16 float4 per row
            float di = g_dinv[base + row];
            float4 v = acc4[i];
            float4 b = bc4[i & 15];
            v.x = fmaxf(fmaf(v.x, di, b.x), 0.f);
            v.y = fmaxf(fmaf(v.y, di, b.y), 0.f);
            v.z = fmaxf(fmaf(v.z, di, b.z), 0.f);
            v.w = fmaxf(fmaf(v.w, di, b.w), 0.f);
            hs4[i] = v;
        }
    }
    __syncthreads();

    float g0[4] = {0.f, 0.f, 0.f, 0.f};
    float g1[4] = {0.f, 0.f, 0.f, 0.f};
#pragma unroll
    for (int mg = 0; mg < HH / 4; mg++) {
        float4 v0 = *(const float4*)&hs[n0 * HH + mg * 4];
        float4 v1 = *(const float4*)&hs[(n0 + 1) * HH + mg * 4];
        const float* p0 = (const float*)&v0;
        const float* p1 = (const float*)&v1;
#pragma unroll
        for (int mm = 0; mm < 4; mm++) {
            float4 w = *(const float4*)&sWc[(mg * 4 + mm) * HH + j0];
            float x0 = p0[mm], x1 = p1[mm];
            g0[0] = fmaf(x0, w.x, g0[0]); g0[1] = fmaf(x0, w.y, g0[1]);
            g0[2] = fmaf(x0, w.z, g0[2]); g0[3] = fmaf(x0, w.w, g0[3]);
            g1[0] = fmaf(x1, w.x, g1[0]); g1[1] = fmaf(x1, w.y, g1[1]);
            g1[2] = fmaf(x1, w.z, g1[2]); g1[3] = fmaf(x1, w.w, g1[3]);
        }
    }
    {
        float d0 = g_dinv[base + n0];
        float d1 = g_dinv[base + n0 + 1];
        float4 o0 = make_float4(g0[0] * d0, g0[1] * d0, g0[2] * d0, g0[3] * d0);
        float4 o1 = make_float4(g1[0] * d1, g1[1] * d1, g1[2] * d1, g1[3] * d1);
        long r0 = (long)(base + n0) * HH + j0;
        long r1 = (long)(base + n0 + 1) * HH + j0;
        *(float4*)&g_g[r0] = o0;  *(float4*)&g_acc[r0] = o0;
        *(float4*)&g_g[r1] = o1;  *(float4*)&g_acc[r1] = o1;
    }
}

// ---------------- K5: h2 = relu(acc*dinv + bc2); a,b = h2 @ Wp1[0:128] -------
__global__ __launch_bounds__(256) void k_node_final(const float* __restrict__ bc2,
                                                    const float* __restrict__ Wp1) {
    const int tid = threadIdx.x;
    const int jg = tid & 15;
    const int j0 = jg * 4;
    const int ys = tid >> 4;
    const int n0 = ys * 2;
    const int base = blockIdx.x * NPB;

    __shared__ float sWa[HH * HH];     // 16 KB
    __shared__ float sWb[HH * HH];     // 16 KB
    __shared__ float hs[NPB * HH];     // 8 KB

    cp4(sWa, Wp1, HH * HH, tid);
    cp4(sWb, Wp1 + HH * HH, HH * HH, tid);
    {
        const float4* acc4 = (const float4*)&g_acc[(long)base * HH];
        const float4* bc4 = (const float4*)bc2;
        float4* hs4 = (float4*)hs;
        for (int i = tid; i < NPB * HH / 4; i += 256) {
            int row = i >> 4;
            float di = g_dinv[base + row];
            float4 v = acc4[i];
            float4 b = bc4[i & 15];
            v.x = fmaxf(fmaf(v.x, di, b.x), 0.f);
            v.y = fmaxf(fmaf(v.y, di, b.y), 0.f);
            v.z = fmaxf(fmaf(v.z, di, b.z), 0.f);
            v.w = fmaxf(fmaf(v.w, di, b.w), 0.f);
            hs4[i] = v;
        }
    }
    __syncthreads();

    float A0[4] = {0.f, 0.f, 0.f, 0.f};
    float A1[4] = {0.f, 0.f, 0.f, 0.f};
    float B0[4] = {0.f, 0.f, 0.f, 0.f};
    float B1[4] = {0.f, 0.f, 0.f, 0.f};
#pragma unroll
    for (int mg = 0; mg < HH / 4; mg++) {
        float4 v0 = *(const float4*)&hs[n0 * HH + mg * 4];
        float4 v1 = *(const float4*)&hs[(n0 + 1) * HH + mg * 4];
        const float* p0 = (const float*)&v0;
        const float* p1 = (const float*)&v1;
#pragma unroll
        for (int mm = 0; mm < 4; mm++) {
            int m = mg * 4 + mm;
            float4 wa = *(const float4*)&sWa[m * HH + j0];
            float4 wb = *(const float4*)&sWb[m * HH + j0];
            float x0 = p0[mm], x1 = p1[mm];
            A0[0] = fmaf(x0, wa.x, A0[0]); A0[1] = fmaf(x0, wa.y, A0[1]);
            A0[2] = fmaf(x0, wa.z, A0[2]); A0[3] = fmaf(x0, wa.w, A0[3]);
            A1[0] = fmaf(x1, wa.x, A1[0]); A1[1] = fmaf(x1, wa.y, A1[1]);
            A1[2] = fmaf(x1, wa.z, A1[2]); A1[3] = fmaf(x1, wa.w, A1[3]);
            B0[0] = fmaf(x0, wb.x, B0[0]); B0[1] = fmaf(x0, wb.y, B0[1]);
            B0[2] = fmaf(x0, wb.z, B0[2]); B0[3] = fmaf(x0, wb.w, B0[3]);
            B1[0] = fmaf(x1, wb.x, B1[0]); B1[1] = fmaf(x1, wb.y, B1[1]);
            B1[2] = fmaf(x1, wb.z, B1[2]); B1[3] = fmaf(x1, wb.w, B1[3]);
        }
    }
    {
        long r0 = (long)(base + n0) * HH + j0;
        long r1 = (long)(base + n0 + 1) * HH + j0;
        *(float4*)&g_a[r0] = make_float4(A0[0], A0[1], A0[2], A0[3]);
        *(float4*)&g_a[r1] = make_float4(A1[0], A1[1], A1[2], A1[3]);
        *(float4*)&g_b[r0] = make_float4(B0[0], B0[1], B0[2], B0[3]);
        *(float4*)&g_b[r1] = make_float4(B1[0], B1[1], B1[2], B1[3]);
    }
}

// ---------------- K6: per-edge output ----------------------------------------
__global__ __launch_bounds__(256) void k_edge_out(const int* __restrict__ ei,
                           const float* __restrict__ eattr,
                           const float* __restrict__ Wp1,
                           const float* __restrict__ bp1,
                           const float* __restrict__ wp2,
                           const float* __restrict__ bp2,
                           float* __restrict__ out) {
    long long gid = (long long)blockIdx.x * blockDim.x + threadIdx.x;
    int e = (int)(gid >> 4);
    if (e >= EE) return;
    int p = (int)(gid & 15);
    int j0 = p * 4;

    int s = __ldg(&ei[e]);
    int d = __ldg(&ei[EE + e]);

    float eav = (p < FE) ? __ldg(&eattr[(long)e * FE + p]) : 0.0f;

    float4 av = __ldg(reinterpret_cast<const float4*>(&g_a[(long)s * HH]) + p);
    float4 bv = __ldg(reinterpret_cast<const float4*>(&g_b[(long)d * HH]) + p);

    float4 c = __ldg(reinterpret_cast<const float4*>(bp1) + p);
#pragma unroll
    for (int k = 0; k < FE; k++) {
        float ek = __shfl_sync(0xffffffffu, eav, k, 16);
        float4 w = __ldg(reinterpret_cast<const float4*>(&Wp1[(128 + k) * HH + j0]));
        c.x = fmaf(ek, w.x, c.x);
        c.y = fmaf(ek, w.y, c.y);
        c.z = fmaf(ek, w.z, c.z);
        c.w = fmaf(ek, w.w, c.w);
    }

    float4 z;
    z.x = fmaxf(av.x + bv.x + c.x, 0.0f);
    z.y = fmaxf(av.y + bv.y + c.y, 0.0f);
    z.z = fmaxf(av.z + bv.z + c.z, 0.0f);
    z.w = fmaxf(av.w + bv.w + c.w, 0.0f);

    float4 w2 = __ldg(reinterpret_cast<const float4*>(wp2) + p);
    float part = z.x * w2.x + z.y * w2.y + z.z * w2.z + z.w * w2.w;

#pragma unroll
    for (int off = 8; off >= 1; off >>= 1)
        part += __shfl_down_sync(0xffffffffu, part, off, 16);

    if (p == 0) out[e] = part + __ldg(bp2);
}

// ---------------- host launcher ----------------------------------------------
extern "C" void kernel_launch(void* const* d_in, const int* in_sizes, int n_in,
                              void* d_out, int out_size) {
    const float* x       = (const float*)d_in[0];
    const float* eattr   = (const float*)d_in[1];
    const float* We      = (const float*)d_in[2];
    const float* be      = (const float*)d_in[3];
    const float* Wc1     = (const float*)d_in[4];
    const float* bc1     = (const float*)d_in[5];
    const float* Wc2     = (const float*)d_in[6];
    const float* bc2     = (const float*)d_in[7];
    const float* Wp1     = (const float*)d_in[8];
    const float* bp1     = (const float*)d_in[9];
    const float* wp2     = (const float*)d_in[10];
    const float* bp2     = (const float*)d_in[11];
    const int*   ei      = (const int*)d_in[12];
    float* out = (float*)d_out;

    k_deg_init<<<(NN + 255) / 256, 256>>>();
    k_deg<<<(EE + 255) / 256, 256>>>(ei);
    k_dinv<<<(NN + 255) / 256, 256>>>();

    int ngrid = NN / NPB;  // 3125

    k_embed<<<ngrid, 256>>>(x, We, be, Wc1);

    long long st = (long long)EE * 16;
    int sgrid = (int)((st + 255) / 256);
    k_scatter<<<sgrid, 256>>>(ei);

    k_mid<<<ngrid, 256>>>(bc1, Wc2);

    k_scatter<<<sgrid, 256>>>(ei);

    k_node_final<<<ngrid, 256>>>(bc2, Wp1);

    k_edge_out<<<sgrid, 256>>>(ei, eattr, Wp1, bp1, wp2, bp2, out);
}

// round 5
// speedup vs baseline: 1.8776x; 1.4526x over previous
#include <cuda_runtime.h>
#include <cuda_bf16.h>
#include <stdint.h>

#define NN 100000
#define EE 1600000
#define FN 32
#define FE 8
#define HH 64
#define NPB 32
#define NB_SCAN 391   // ceil(NN/256)

// ---------------- scratch (device globals) ------------------------------------
__device__ float g_g[NN * HH];    // g' = (h@W) * dinv[src-side]
__device__ float g_acc[NN * HH];  // aggregated (self + in-edges)
__device__ float g_a[NN * HH];
__device__ float g_b[NN * HH];
__device__ float g_dinv[NN];
__device__ int   g_degi[NN];
__device__ int   g_off[NN];
__device__ int   g_offtmp[NN];
__device__ int   g_cur[NN];
__device__ int   g_bsum[512];
__device__ int   g_bscan[512];
__device__ int   g_csr[EE];       // src node of each in-edge, grouped by dst

// ---------------- degree / norm / CSR build -----------------------------------
__global__ void k_zero() {
    int n = blockIdx.x * blockDim.x + threadIdx.x;
    if (n < NN) g_degi[n] = 0;
}

__global__ void k_deg(const int* __restrict__ ei) {
    int e = blockIdx.x * blockDim.x + threadIdx.x;
    if (e < EE) atomicAdd(&g_degi[__ldg(&ei[EE + e])], 1);
}

__global__ void k_dinv() {
    int n = blockIdx.x * blockDim.x + threadIdx.x;
    if (n < NN) g_dinv[n] = rsqrtf((float)(g_degi[n] + 1));  // +1 self loop
}

// block-level inclusive scan (Hillis-Steele), emit exclusive + block sums
__global__ void k_scanA() {
    __shared__ int sm[256];
    int t = threadIdx.x;
    int idx = blockIdx.x * 256 + t;
    int v = (idx < NN) ? g_degi[idx] : 0;
    sm[t] = v;
    __syncthreads();
#pragma unroll
    for (int o = 1; o < 256; o <<= 1) {
        int x = (t >= o) ? sm[t - o] : 0;
        __syncthreads();
        sm[t] += x;
        __syncthreads();
    }
    if (idx < NN) g_offtmp[idx] = sm[t] - v;
    if (t == 255) g_bsum[blockIdx.x] = sm[255];
}

__global__ void k_scanB() {
    __shared__ int sm[512];
    int t = threadIdx.x;
    int v = (t < NB_SCAN) ? g_bsum[t] : 0;
    sm[t] = v;
    __syncthreads();
#pragma unroll
    for (int o = 1; o < 512; o <<= 1) {
        int x = (t >= o) ? sm[t - o] : 0;
        __syncthreads();
        sm[t] += x;
        __syncthreads();
    }
    g_bscan[t] = sm[t] - v;
}

__global__ void k_scanC() {
    int idx = blockIdx.x * blockDim.x + threadIdx.x;
    if (idx < NN) {
        int o = g_offtmp[idx] + g_bscan[idx >> 8];
        g_off[idx] = o;
        g_cur[idx] = o;
    }
}

__global__ void k_fill(const int* __restrict__ ei) {
    int e = blockIdx.x * blockDim.x + threadIdx.x;
    if (e < EE) {
        int d = __ldg(&ei[EE + e]);
        int pos = atomicAdd(&g_cur[d], 1);
        g_csr[pos] = __ldg(&ei[e]);
    }
}

// float4 smem copy helper
__device__ __forceinline__ void cp4(float* dst, const float* src, int nfl, int tid) {
    const float4* s = (const float4*)src;
    float4* d = (float4*)dst;
    for (int i = tid; i < nfl / 4; i += 256) d[i] = s[i];
}

// ---------------- K1: h0 = relu(x@We+be); g1' = (h0@Wc1)*dinv ----------------
__global__ __launch_bounds__(256) void k_embed(const float* __restrict__ x,
                                               const float* __restrict__ We,
                                               const float* __restrict__ be,
                                               const float* __restrict__ Wc1) {
    const int tid = threadIdx.x;
    const int jg = tid & 15;
    const int j0 = jg * 4;
    const int ys = tid >> 4;
    const int n0 = ys * 2;
    const int base = blockIdx.x * NPB;

    __shared__ float sWe[FN * HH];
    __shared__ float sWc[HH * HH];
    __shared__ float xs[NPB * FN];
    __shared__ float hs[NPB * HH];

    cp4(sWe, We, FN * HH, tid);
    cp4(sWc, Wc1, HH * HH, tid);
    cp4(xs, x + (long)base * FN, NPB * FN, tid);
    __syncthreads();

    float a0[4] = {0.f, 0.f, 0.f, 0.f};
    float a1[4] = {0.f, 0.f, 0.f, 0.f};
#pragma unroll
    for (int mg = 0; mg < FN / 4; mg++) {
        float4 v0 = *(const float4*)&xs[n0 * FN + mg * 4];
        float4 v1 = *(const float4*)&xs[(n0 + 1) * FN + mg * 4];
        const float* p0 = (const float*)&v0;
        const float* p1 = (const float*)&v1;
#pragma unroll
        for (int mm = 0; mm < 4; mm++) {
            float4 w = *(const float4*)&sWe[(mg * 4 + mm) * HH + j0];
            float x0 = p0[mm], x1 = p1[mm];
            a0[0] = fmaf(x0, w.x, a0[0]); a0[1] = fmaf(x0, w.y, a0[1]);
            a0[2] = fmaf(x0, w.z, a0[2]); a0[3] = fmaf(x0, w.w, a0[3]);
            a1[0] = fmaf(x1, w.x, a1[0]); a1[1] = fmaf(x1, w.y, a1[1]);
            a1[2] = fmaf(x1, w.z, a1[2]); a1[3] = fmaf(x1, w.w, a1[3]);
        }
    }
    {
        float4 bb = *(const float4*)&be[j0];
        float4 h0, h1;
        h0.x = fmaxf(a0[0] + bb.x, 0.f); h0.y = fmaxf(a0[1] + bb.y, 0.f);
        h0.z = fmaxf(a0[2] + bb.z, 0.f); h0.w = fmaxf(a0[3] + bb.w, 0.f);
        h1.x = fmaxf(a1[0] + bb.x, 0.f); h1.y = fmaxf(a1[1] + bb.y, 0.f);
        h1.z = fmaxf(a1[2] + bb.z, 0.f); h1.w = fmaxf(a1[3] + bb.w, 0.f);
        *(float4*)&hs[n0 * HH + j0] = h0;
        *(float4*)&hs[(n0 + 1) * HH + j0] = h1;
    }
    __syncthreads();

    float g0[4] = {0.f, 0.f, 0.f, 0.f};
    float g1[4] = {0.f, 0.f, 0.f, 0.f};
#pragma unroll
    for (int mg = 0; mg < HH / 4; mg++) {
        float4 v0 = *(const float4*)&hs[n0 * HH + mg * 4];
        float4 v1 = *(const float4*)&hs[(n0 + 1) * HH + mg * 4];
        const float* p0 = (const float*)&v0;
        const float* p1 = (const float*)&v1;
#pragma unroll
        for (int mm = 0; mm < 4; mm++) {
            float4 w = *(const float4*)&sWc[(mg * 4 + mm) * HH + j0];
            float x0 = p0[mm], x1 = p1[mm];
            g0[0] = fmaf(x0, w.x, g0[0]); g0[1] = fmaf(x0, w.y, g0[1]);
            g0[2] = fmaf(x0, w.z, g0[2]); g0[3] = fmaf(x0, w.w, g0[3]);
            g1[0] = fmaf(x1, w.x, g1[0]); g1[1] = fmaf(x1, w.y, g1[1]);
            g1[2] = fmaf(x1, w.z, g1[2]); g1[3] = fmaf(x1, w.w, g1[3]);
        }
    }
    {
        float d0 = g_dinv[base + n0];
        float d1 = g_dinv[base + n0 + 1];
        long r0 = (long)(base + n0) * HH + j0;
        long r1 = (long)(base + n0 + 1) * HH + j0;
        *(float4*)&g_g[r0] = make_float4(g0[0] * d0, g0[1] * d0, g0[2] * d0, g0[3] * d0);
        *(float4*)&g_g[r1] = make_float4(g1[0] * d1, g1[1] * d1, g1[2] * d1, g1[3] * d1);
    }
}

// ---------------- gather-aggregate: acc[n] = g'[n] + sum_{s->n} g'[s] --------
// 16 threads per node, 16 nodes per block. No atomics.
__global__ __launch_bounds__(256) void k_gather() {
    const int tid = threadIdx.x;
    const int p = tid & 15;
    const int grp = tid >> 4;
    const int n = blockIdx.x * 16 + grp;
    const unsigned hm = 0xFFFFu << (tid & 16);

    float4 acc = *(const float4*)&g_g[(long)n * HH + p * 4];  // self loop
    const int beg = g_off[n];
    const int end = beg + g_degi[n];

    for (int b = beg; b < end; b += 16) {
        int rem = end - b;
        int cnt = rem < 16 ? rem : 16;
        int myi = (p < cnt) ? __ldg(&g_csr[b + p]) : 0;
        for (int k = 0; k < cnt; k++) {
            int s = __shfl_sync(hm, myi, k, 16);
            float4 v = __ldg(reinterpret_cast<const float4*>(&g_g[(long)s * HH]) + p);
            acc.x += v.x; acc.y += v.y; acc.z += v.z; acc.w += v.w;
        }
    }
    *(float4*)&g_acc[(long)n * HH + p * 4] = acc;
}

// ---------------- K3: h1 = relu(acc*dinv + bc1); g2' = (h1@Wc2)*dinv ---------
__global__ __launch_bounds__(256) void k_mid(const float* __restrict__ bc,
                                             const float* __restrict__ Wc) {
    const int tid = threadIdx.x;
    const int jg = tid & 15;
    const int j0 = jg * 4;
    const int ys = tid >> 4;
    const int n0 = ys * 2;
    const int base = blockIdx.x * NPB;

    __shared__ float sWc[HH * HH];
    __shared__ float hs[NPB * HH];

    cp4(sWc, Wc, HH * HH, tid);
    {
        const float4* acc4 = (const float4*)&g_acc[(long)base * HH];
        const float4* bc4 = (const float4*)bc;
        float4* hs4 = (float4*)hs;
        for (int i = tid; i < NPB * HH / 4; i += 256) {
            int row = i >> 4;
            float di = g_dinv[base + row];
            float4 v = acc4[i];
            float4 b = bc4[i & 15];
            v.x = fmaxf(fmaf(v.x, di, b.x), 0.f);
            v.y = fmaxf(fmaf(v.y, di, b.y), 0.f);
            v.z = fmaxf(fmaf(v.z, di, b.z), 0.f);
            v.w = fmaxf(fmaf(v.w, di, b.w), 0.f);
            hs4[i] = v;
        }
    }
    __syncthreads();

    float g0[4] = {0.f, 0.f, 0.f, 0.f};
    float g1[4] = {0.f, 0.f, 0.f, 0.f};
#pragma unroll
    for (int mg = 0; mg < HH / 4; mg++) {
        float4 v0 = *(const float4*)&hs[n0 * HH + mg * 4];
        float4 v1 = *(const float4*)&hs[(n0 + 1) * HH + mg * 4];
        const float* p0 = (const float*)&v0;
        const float* p1 = (const float*)&v1;
#pragma unroll
        for (int mm = 0; mm < 4; mm++) {
            float4 w = *(const float4*)&sWc[(mg * 4 + mm) * HH + j0];
            float x0 = p0[mm], x1 = p1[mm];
            g0[0] = fmaf(x0, w.x, g0[0]); g0[1] = fmaf(x0, w.y, g0[1]);
            g0[2] = fmaf(x0, w.z, g0[2]); g0[3] = fmaf(x0, w.w, g0[3]);
            g1[0] = fmaf(x1, w.x, g1[0]); g1[1] = fmaf(x1, w.y, g1[1]);
            g1[2] = fmaf(x1, w.z, g1[2]); g1[3] = fmaf(x1, w.w, g1[3]);
        }
    }
    {
        float d0 = g_dinv[base + n0];
        float d1 = g_dinv[base + n0 + 1];
        long r0 = (long)(base + n0) * HH + j0;
        long r1 = (long)(base + n0 + 1) * HH + j0;
        *(float4*)&g_g[r0] = make_float4(g0[0] * d0, g0[1] * d0, g0[2] * d0, g0[3] * d0);
        *(float4*)&g_g[r1] = make_float4(g1[0] * d1, g1[1] * d1, g1[2] * d1, g1[3] * d1);
    }
}

// ---------------- K5: h2 = relu(acc*dinv + bc2); a,b = h2 @ Wp1[0:128] -------
__global__ __launch_bounds__(256) void k_node_final(const float* __restrict__ bc2,
                                                    const float* __restrict__ Wp1) {
    const int tid = threadIdx.x;
    const int jg = tid & 15;
    const int j0 = jg * 4;
    const int ys = tid >> 4;
    const int n0 = ys * 2;
    const int base = blockIdx.x * NPB;

    __shared__ float sWa[HH * HH];
    __shared__ float sWb[HH * HH];
    __shared__ float hs[NPB * HH];

    cp4(sWa, Wp1, HH * HH, tid);
    cp4(sWb, Wp1 + HH * HH, HH * HH, tid);
    {
        const float4* acc4 = (const float4*)&g_acc[(long)base * HH];
        const float4* bc4 = (const float4*)bc2;
        float4* hs4 = (float4*)hs;
        for (int i = tid; i < NPB * HH / 4; i += 256) {
            int row = i >> 4;
            float di = g_dinv[base + row];
            float4 v = acc4[i];
            float4 b = bc4[i & 15];
            v.x = fmaxf(fmaf(v.x, di, b.x), 0.f);
            v.y = fmaxf(fmaf(v.y, di, b.y), 0.f);
            v.z = fmaxf(fmaf(v.z, di, b.z), 0.f);
            v.w = fmaxf(fmaf(v.w, di, b.w), 0.f);
            hs4[i] = v;
        }
    }
    __syncthreads();

    float A0[4] = {0.f, 0.f, 0.f, 0.f};
    float A1[4] = {0.f, 0.f, 0.f, 0.f};
    float B0[4] = {0.f, 0.f, 0.f, 0.f};
    float B1[4] = {0.f, 0.f, 0.f, 0.f};
#pragma unroll
    for (int mg = 0; mg < HH / 4; mg++) {
        float4 v0 = *(const float4*)&hs[n0 * HH + mg * 4];
        float4 v1 = *(const float4*)&hs[(n0 + 1) * HH + mg * 4];
        const float* p0 = (const float*)&v0;
        const float* p1 = (const float*)&v1;
#pragma unroll
        for (int mm = 0; mm < 4; mm++) {
            int m = mg * 4 + mm;
            float4 wa = *(const float4*)&sWa[m * HH + j0];
            float4 wb = *(const float4*)&sWb[m * HH + j0];
            float x0 = p0[mm], x1 = p1[mm];
            A0[0] = fmaf(x0, wa.x, A0[0]); A0[1] = fmaf(x0, wa.y, A0[1]);
            A0[2] = fmaf(x0, wa.z, A0[2]); A0[3] = fmaf(x0, wa.w, A0[3]);
            A1[0] = fmaf(x1, wa.x, A1[0]); A1[1] = fmaf(x1, wa.y, A1[1]);
            A1[2] = fmaf(x1, wa.z, A1[2]); A1[3] = fmaf(x1, wa.w, A1[3]);
            B0[0] = fmaf(x0, wb.x, B0[0]); B0[1] = fmaf(x0, wb.y, B0[1]);
            B0[2] = fmaf(x0, wb.z, B0[2]); B0[3] = fmaf(x0, wb.w, B0[3]);
            B1[0] = fmaf(x1, wb.x, B1[0]); B1[1] = fmaf(x1, wb.y, B1[1]);
            B1[2] = fmaf(x1, wb.z, B1[2]); B1[3] = fmaf(x1, wb.w, B1[3]);
        }
    }
    {
        long r0 = (long)(base + n0) * HH + j0;
        long r1 = (long)(base + n0 + 1) * HH + j0;
        *(float4*)&g_a[r0] = make_float4(A0[0], A0[1], A0[2], A0[3]);
        *(float4*)&g_a[r1] = make_float4(A1[0], A1[1], A1[2], A1[3]);
        *(float4*)&g_b[r0] = make_float4(B0[0], B0[1], B0[2], B0[3]);
        *(float4*)&g_b[r1] = make_float4(B1[0], B1[1], B1[2], B1[3]);
    }
}

// ---------------- K6: per-edge output, 4 edges per 16-thread group -----------
#define EPT 4
__global__ __launch_bounds__(256) void k_edge_out(const int* __restrict__ ei,
                           const float* __restrict__ eattr,
                           const float* __restrict__ Wp1,
                           const float* __restrict__ bp1,
                           const float* __restrict__ wp2,
                           const float* __restrict__ bp2,
                           float* __restrict__ out) {
    const int tid = threadIdx.x;
    const int p = tid & 15;
    const int grp = tid >> 4;
    const int j0 = p * 4;
    long e0 = ((long)blockIdx.x * 16 + grp) * EPT;

    float4 wt[FE];
#pragma unroll
    for (int k = 0; k < FE; k++)
        wt[k] = __ldg(reinterpret_cast<const float4*>(&Wp1[(2 * HH + k) * HH + j0]));
    float4 c0 = __ldg(reinterpret_cast<const float4*>(bp1) + p);
    float4 w2 = __ldg(reinterpret_cast<const float4*>(wp2) + p);
    float bias2 = __ldg(bp2);

#pragma unroll
    for (int t = 0; t < EPT; t++) {
        long e = e0 + t;
        int s = __ldg(&ei[e]);
        int d = __ldg(&ei[EE + e]);
        float eav = (p < FE) ? __ldg(&eattr[e * FE + p]) : 0.0f;

        float4 av = __ldg(reinterpret_cast<const float4*>(&g_a[(long)s * HH]) + p);
        float4 bv = __ldg(reinterpret_cast<const float4*>(&g_b[(long)d * HH]) + p);

        float4 c = c0;
#pragma unroll
        for (int k = 0; k < FE; k++) {
            float ek = __shfl_sync(0xffffffffu, eav, k, 16);
            c.x = fmaf(ek, wt[k].x, c.x);
            c.y = fmaf(ek, wt[k].y, c.y);
            c.z = fmaf(ek, wt[k].z, c.z);
            c.w = fmaf(ek, wt[k].w, c.w);
        }

        float4 z;
        z.x = fmaxf(av.x + bv.x + c.x, 0.0f);
        z.y = fmaxf(av.y + bv.y + c.y, 0.0f);
        z.z = fmaxf(av.z + bv.z + c.z, 0.0f);
        z.w = fmaxf(av.w + bv.w + c.w, 0.0f);

        float part = z.x * w2.x + z.y * w2.y + z.z * w2.z + z.w * w2.w;
#pragma unroll
        for (int off = 8; off >= 1; off >>= 1)
            part += __shfl_down_sync(0xffffffffu, part, off, 16);

        if (p == 0) out[e] = part + bias2;
    }
}

// ---------------- host launcher ----------------------------------------------
extern "C" void kernel_launch(void* const* d_in, const int* in_sizes, int n_in,
                              void* d_out, int out_size) {
    const float* x     = (const float*)d_in[0];
    const float* eattr = (const float*)d_in[1];
    const float* We    = (const float*)d_in[2];
    const float* be    = (const float*)d_in[3];
    const float* Wc1   = (const float*)d_in[4];
    const float* bc1   = (const float*)d_in[5];
    const float* Wc2   = (const float*)d_in[6];
    const float* bc2   = (const float*)d_in[7];
    const float* Wp1   = (const float*)d_in[8];
    const float* bp1   = (const float*)d_in[9];
    const float* wp2   = (const float*)d_in[10];
    const float* bp2   = (const float*)d_in[11];
    const int*   ei    = (const int*)d_in[12];
    float* out = (float*)d_out;

    // CSR build
    k_zero<<<(NN + 255) / 256, 256>>>();
    k_deg<<<(EE + 255) / 256, 256>>>(ei);
    k_dinv<<<(NN + 255) / 256, 256>>>();
    k_scanA<<<NB_SCAN, 256>>>();
    k_scanB<<<1, 512>>>();
    k_scanC<<<(NN + 255) / 256, 256>>>();
    k_fill<<<(EE + 255) / 256, 256>>>(ei);

    int ngrid = NN / NPB;          // 3125
    int ggrid = (NN + 15) / 16;    // 6250

    k_embed<<<ngrid, 256>>>(x, We, be, Wc1);
    k_gather<<<ggrid, 256>>>();
    k_mid<<<ngrid, 256>>>(bc1, Wc2);
    k_gather<<<ggrid, 256>>>();
    k_node_final<<<ngrid, 256>>>(bc2, Wp1);

    k_edge_out<<<EE / (16 * EPT), 256>>>(ei, eattr, Wp1, bp1, wp2, bp2, out);
}

// round 6
// speedup vs baseline: 2.0365x; 1.0846x over previous
#include <cuda_runtime.h>
#include <cuda_bf16.h>
#include <stdint.h>

#define NN 100000
#define EE 1600000
#define FN 32
#define FE 8
#define HH 64
#define NPB 32
#define NB_SCAN 391   // ceil(NN/256)

// ---------------- scratch (device globals) ------------------------------------
__device__ float g_g[NN * HH];    // g' = (h@W) * dinv[src-side]
__device__ float g_acc[NN * HH];  // aggregated (self + in-edges)
__device__ float g_a[NN * HH];
__device__ float g_b[NN * HH];
__device__ float g_dinv[NN];
__device__ int   g_degi[NN];
__device__ int   g_off[NN];
__device__ int   g_offtmp[NN];
__device__ int   g_cur[NN];
__device__ int   g_bsum[512];
__device__ int   g_bscan[512];
__device__ int   g_csr[EE];       // src node of each in-edge, grouped by dst

// ---------------- degree / norm / CSR build -----------------------------------
__global__ void k_zero() {
    int n = blockIdx.x * blockDim.x + threadIdx.x;
    if (n < NN) g_degi[n] = 0;
}

__global__ void k_deg(const int* __restrict__ ei) {
    int e = blockIdx.x * blockDim.x + threadIdx.x;
    if (e < EE) atomicAdd(&g_degi[__ldg(&ei[EE + e])], 1);
}

// block-level inclusive scan (Hillis-Steele), emit exclusive + block sums
__global__ void k_scanA() {
    __shared__ int sm[256];
    int t = threadIdx.x;
    int idx = blockIdx.x * 256 + t;
    int v = (idx < NN) ? g_degi[idx] : 0;
    sm[t] = v;
    __syncthreads();
#pragma unroll
    for (int o = 1; o < 256; o <<= 1) {
        int x = (t >= o) ? sm[t - o] : 0;
        __syncthreads();
        sm[t] += x;
        __syncthreads();
    }
    if (idx < NN) g_offtmp[idx] = sm[t] - v;
    if (t == 255) g_bsum[blockIdx.x] = sm[255];
}

__global__ void k_scanB() {
    __shared__ int sm[512];
    int t = threadIdx.x;
    int v = (t < NB_SCAN) ? g_bsum[t] : 0;
    sm[t] = v;
    __syncthreads();
#pragma unroll
    for (int o = 1; o < 512; o <<= 1) {
        int x = (t >= o) ? sm[t - o] : 0;
        __syncthreads();
        sm[t] += x;
        __syncthreads();
    }
    g_bscan[t] = sm[t] - v;
}

__global__ void k_scanC() {
    int idx = blockIdx.x * blockDim.x + threadIdx.x;
    if (idx < NN) {
        int o = g_offtmp[idx] + g_bscan[idx >> 8];
        g_off[idx] = o;
        g_cur[idx] = o;
        g_dinv[idx] = rsqrtf((float)(g_degi[idx] + 1));  // +1 self loop
    }
}

__global__ void k_fill(const int* __restrict__ ei) {
    int e = blockIdx.x * blockDim.x + threadIdx.x;
    if (e < EE) {
        int d = __ldg(&ei[EE + e]);
        int pos = atomicAdd(&g_cur[d], 1);
        g_csr[pos] = __ldg(&ei[e]);
    }
}

// float4 smem copy helper (stride = block threads)
__device__ __forceinline__ void cp4(float* dst, const float* src, int nfl,
                                    int tid, int nt) {
    const float4* s = (const float4*)src;
    float4* d = (float4*)dst;
    for (int i = tid; i < nfl / 4; i += nt) d[i] = s[i];
}

// ================== node GEMM kernels: 128 threads, 32 nodes/block ===========
// jg = tid&15 (4 output features), ys = tid>>4 (0..7, 4 nodes each).

// ---------------- K1: h0 = relu(x@We+be); g1' = (h0@Wc1)*dinv ----------------
__global__ __launch_bounds__(128) void k_embed(const float* __restrict__ x,
                                               const float* __restrict__ We,
                                               const float* __restrict__ be,
                                               const float* __restrict__ Wc1) {
    const int tid = threadIdx.x;
    const int j0 = (tid & 15) * 4;
    const int n0 = (tid >> 4) * 4;
    const int base = blockIdx.x * NPB;

    __shared__ float sWe[FN * HH];     // 8 KB
    __shared__ float sWc[HH * HH];     // 16 KB
    __shared__ float xs[NPB * FN];     // 4 KB
    __shared__ float hs[NPB * HH];     // 8 KB

    cp4(sWe, We, FN * HH, tid, 128);
    cp4(sWc, Wc1, HH * HH, tid, 128);
    cp4(xs, x + (long)base * FN, NPB * FN, tid, 128);
    __syncthreads();

    // stage 1
    float a[4][4] = {};
#pragma unroll
    for (int mg = 0; mg < FN / 4; mg++) {
        float4 v[4];
#pragma unroll
        for (int r = 0; r < 4; r++) v[r] = *(const float4*)&xs[(n0 + r) * FN + mg * 4];
#pragma unroll
        for (int mm = 0; mm < 4; mm++) {
            float4 w = *(const float4*)&sWe[(mg * 4 + mm) * HH + j0];
#pragma unroll
            for (int r = 0; r < 4; r++) {
                float xv = ((const float*)&v[r])[mm];
                a[r][0] = fmaf(xv, w.x, a[r][0]);
                a[r][1] = fmaf(xv, w.y, a[r][1]);
                a[r][2] = fmaf(xv, w.z, a[r][2]);
                a[r][3] = fmaf(xv, w.w, a[r][3]);
            }
        }
    }
    {
        float4 bb = *(const float4*)&be[j0];
#pragma unroll
        for (int r = 0; r < 4; r++) {
            float4 h;
            h.x = fmaxf(a[r][0] + bb.x, 0.f);
            h.y = fmaxf(a[r][1] + bb.y, 0.f);
            h.z = fmaxf(a[r][2] + bb.z, 0.f);
            h.w = fmaxf(a[r][3] + bb.w, 0.f);
            *(float4*)&hs[(n0 + r) * HH + j0] = h;
        }
    }
    __syncthreads();

    // stage 2
    float g[4][4] = {};
#pragma unroll
    for (int mg = 0; mg < HH / 4; mg++) {
        float4 v[4];
#pragma unroll
        for (int r = 0; r < 4; r++) v[r] = *(const float4*)&hs[(n0 + r) * HH + mg * 4];
#pragma unroll
        for (int mm = 0; mm < 4; mm++) {
            float4 w = *(const float4*)&sWc[(mg * 4 + mm) * HH + j0];
#pragma unroll
            for (int r = 0; r < 4; r++) {
                float xv = ((const float*)&v[r])[mm];
                g[r][0] = fmaf(xv, w.x, g[r][0]);
                g[r][1] = fmaf(xv, w.y, g[r][1]);
                g[r][2] = fmaf(xv, w.z, g[r][2]);
                g[r][3] = fmaf(xv, w.w, g[r][3]);
            }
        }
    }
#pragma unroll
    for (int r = 0; r < 4; r++) {
        float di = g_dinv[base + n0 + r];
        *(float4*)&g_g[(long)(base + n0 + r) * HH + j0] =
            make_float4(g[r][0] * di, g[r][1] * di, g[r][2] * di, g[r][3] * di);
    }
}

// ---------------- gather-aggregate: acc[n] = g'[n] + sum_{s->n} g'[s] --------
__global__ __launch_bounds__(256) void k_gather() {
    const int tid = threadIdx.x;
    const int p = tid & 15;
    const int grp = tid >> 4;
    const int n = blockIdx.x * 16 + grp;
    const unsigned hm = 0xFFFFu << (tid & 16);

    float4 acc = *(const float4*)&g_g[(long)n * HH + p * 4];  // self loop
    const int beg = g_off[n];
    const int end = beg + g_degi[n];

    for (int b = beg; b < end; b += 16) {
        int rem = end - b;
        int cnt = rem < 16 ? rem : 16;
        int myi = (p < cnt) ? __ldg(&g_csr[b + p]) : 0;
        for (int k = 0; k < cnt; k++) {
            int s = __shfl_sync(hm, myi, k, 16);
            float4 v = __ldg(reinterpret_cast<const float4*>(&g_g[(long)s * HH]) + p);
            acc.x += v.x; acc.y += v.y; acc.z += v.z; acc.w += v.w;
        }
    }
    *(float4*)&g_acc[(long)n * HH + p * 4] = acc;
}

// ---------------- K3: h1 = relu(acc*dinv + bc1); g2' = (h1@Wc2)*dinv ---------
__global__ __launch_bounds__(128) void k_mid(const float* __restrict__ bc,
                                             const float* __restrict__ Wc) {
    const int tid = threadIdx.x;
    const int j0 = (tid & 15) * 4;
    const int n0 = (tid >> 4) * 4;
    const int base = blockIdx.x * NPB;

    __shared__ float sWc[HH * HH];     // 16 KB
    __shared__ float hs[NPB * HH];     // 8 KB

    cp4(sWc, Wc, HH * HH, tid, 128);
    {
        const float4* acc4 = (const float4*)&g_acc[(long)base * HH];
        const float4* bc4 = (const float4*)bc;
        float4* hs4 = (float4*)hs;
        for (int i = tid; i < NPB * HH / 4; i += 128) {
            int row = i >> 4;
            float di = g_dinv[base + row];
            float4 v = acc4[i];
            float4 b = bc4[i & 15];
            v.x = fmaxf(fmaf(v.x, di, b.x), 0.f);
            v.y = fmaxf(fmaf(v.y, di, b.y), 0.f);
            v.z = fmaxf(fmaf(v.z, di, b.z), 0.f);
            v.w = fmaxf(fmaf(v.w, di, b.w), 0.f);
            hs4[i] = v;
        }
    }
    __syncthreads();

    float g[4][4] = {};
#pragma unroll
    for (int mg = 0; mg < HH / 4; mg++) {
        float4 v[4];
#pragma unroll
        for (int r = 0; r < 4; r++) v[r] = *(const float4*)&hs[(n0 + r) * HH + mg * 4];
#pragma unroll
        for (int mm = 0; mm < 4; mm++) {
            float4 w = *(const float4*)&sWc[(mg * 4 + mm) * HH + j0];
#pragma unroll
            for (int r = 0; r < 4; r++) {
                float xv = ((const float*)&v[r])[mm];
                g[r][0] = fmaf(xv, w.x, g[r][0]);
                g[r][1] = fmaf(xv, w.y, g[r][1]);
                g[r][2] = fmaf(xv, w.z, g[r][2]);
                g[r][3] = fmaf(xv, w.w, g[r][3]);
            }
        }
    }
#pragma unroll
    for (int r = 0; r < 4; r++) {
        float di = g_dinv[base + n0 + r];
        *(float4*)&g_g[(long)(base + n0 + r) * HH + j0] =
            make_float4(g[r][0] * di, g[r][1] * di, g[r][2] * di, g[r][3] * di);
    }
}

// ---------------- K5: h2 = relu(acc*dinv + bc2); a,b = h2 @ Wp1[0:128] -------
__global__ __launch_bounds__(128) void k_node_final(const float* __restrict__ bc2,
                                                    const float* __restrict__ Wp1) {
    const int tid = threadIdx.x;
    const int j0 = (tid & 15) * 4;
    const int n0 = (tid >> 4) * 4;
    const int base = blockIdx.x * NPB;

    __shared__ float sWa[HH * HH];     // 16 KB
    __shared__ float sWb[HH * HH];     // 16 KB
    __shared__ float hs[NPB * HH];     // 8 KB

    cp4(sWa, Wp1, HH * HH, tid, 128);
    cp4(sWb, Wp1 + HH * HH, HH * HH, tid, 128);
    {
        const float4* acc4 = (const float4*)&g_acc[(long)base * HH];
        const float4* bc4 = (const float4*)bc2;
        float4* hs4 = (float4*)hs;
        for (int i = tid; i < NPB * HH / 4; i += 128) {
            int row = i >> 4;
            float di = g_dinv[base + row];
            float4 v = acc4[i];
            float4 b = bc4[i & 15];
            v.x = fmaxf(fmaf(v.x, di, b.x), 0.f);
            v.y = fmaxf(fmaf(v.y, di, b.y), 0.f);
            v.z = fmaxf(fmaf(v.z, di, b.z), 0.f);
            v.w = fmaxf(fmaf(v.w, di, b.w), 0.f);
            hs4[i] = v;
        }
    }
    __syncthreads();

    float A[4][4] = {};
    float B[4][4] = {};
#pragma unroll
    for (int mg = 0; mg < HH / 4; mg++) {
        float4 v[4];
#pragma unroll
        for (int r = 0; r < 4; r++) v[r] = *(const float4*)&hs[(n0 + r) * HH + mg * 4];
#pragma unroll
        for (int mm = 0; mm < 4; mm++) {
            int m = mg * 4 + mm;
            float4 wa = *(const float4*)&sWa[m * HH + j0];
            float4 wb = *(const float4*)&sWb[m * HH + j0];
#pragma unroll
            for (int r = 0; r < 4; r++) {
                float xv = ((const float*)&v[r])[mm];
                A[r][0] = fmaf(xv, wa.x, A[r][0]);
                A[r][1] = fmaf(xv, wa.y, A[r][1]);
                A[r][2] = fmaf(xv, wa.z, A[r][2]);
                A[r][3] = fmaf(xv, wa.w, A[r][3]);
                B[r][0] = fmaf(xv, wb.x, B[r][0]);
                B[r][1] = fmaf(xv, wb.y, B[r][1]);
                B[r][2] = fmaf(xv, wb.z, B[r][2]);
                B[r][3] = fmaf(xv, wb.w, B[r][3]);
            }
        }
    }
#pragma unroll
    for (int r = 0; r < 4; r++) {
        long rr = (long)(base + n0 + r) * HH + j0;
        *(float4*)&g_a[rr] = make_float4(A[r][0], A[r][1], A[r][2], A[r][3]);
        *(float4*)&g_b[rr] = make_float4(B[r][0], B[r][1], B[r][2], B[r][3]);
    }
}

// ---------------- K6: per-edge output, 4 edges per 16-thread group -----------
#define EPT 4
__global__ __launch_bounds__(256) void k_edge_out(const int* __restrict__ ei,
                           const float* __restrict__ eattr,
                           const float* __restrict__ Wp1,
                           const float* __restrict__ bp1,
                           const float* __restrict__ wp2,
                           const float* __restrict__ bp2,
                           float* __restrict__ out) {
    const int tid = threadIdx.x;
    const int p = tid & 15;
    const int grp = tid >> 4;
    const int j0 = p * 4;
    long e0 = ((long)blockIdx.x * 16 + grp) * EPT;

    float4 wt[FE];
#pragma unroll
    for (int k = 0; k < FE; k++)
        wt[k] = __ldg(reinterpret_cast<const float4*>(&Wp1[(2 * HH + k) * HH + j0]));
    float4 c0 = __ldg(reinterpret_cast<const float4*>(bp1) + p);
    float4 w2 = __ldg(reinterpret_cast<const float4*>(wp2) + p);
    float bias2 = __ldg(bp2);

#pragma unroll
    for (int t = 0; t < EPT; t++) {
        long e = e0 + t;
        int s = __ldg(&ei[e]);
        int d = __ldg(&ei[EE + e]);
        float eav = (p < FE) ? __ldg(&eattr[e * FE + p]) : 0.0f;

        float4 av = __ldg(reinterpret_cast<const float4*>(&g_a[(long)s * HH]) + p);
        float4 bv = __ldg(reinterpret_cast<const float4*>(&g_b[(long)d * HH]) + p);

        float4 c = c0;
#pragma unroll
        for (int k = 0; k < FE; k++) {
            float ek = __shfl_sync(0xffffffffu, eav, k, 16);
            c.x = fmaf(ek, wt[k].x, c.x);
            c.y = fmaf(ek, wt[k].y, c.y);
            c.z = fmaf(ek, wt[k].z, c.z);
            c.w = fmaf(ek, wt[k].w, c.w);
        }

        float4 z;
        z.x = fmaxf(av.x + bv.x + c.x, 0.0f);
        z.y = fmaxf(av.y + bv.y + c.y, 0.0f);
        z.z = fmaxf(av.z + bv.z + c.z, 0.0f);
        z.w = fmaxf(av.w + bv.w + c.w, 0.0f);

        float part = z.x * w2.x + z.y * w2.y + z.z * w2.z + z.w * w2.w;
#pragma unroll
        for (int off = 8; off >= 1; off >>= 1)
            part += __shfl_down_sync(0xffffffffu, part, off, 16);

        if (p == 0) out[e] = part + bias2;
    }
}

// ---------------- host launcher ----------------------------------------------
extern "C" void kernel_launch(void* const* d_in, const int* in_sizes, int n_in,
                              void* d_out, int out_size) {
    const float* x     = (const float*)d_in[0];
    const float* eattr = (const float*)d_in[1];
    const float* We    = (const float*)d_in[2];
    const float* be    = (const float*)d_in[3];
    const float* Wc1   = (const float*)d_in[4];
    const float* bc1   = (const float*)d_in[5];
    const float* Wc2   = (const float*)d_in[6];
    const float* bc2   = (const float*)d_in[7];
    const float* Wp1   = (const float*)d_in[8];
    const float* bp1   = (const float*)d_in[9];
    const float* wp2   = (const float*)d_in[10];
    const float* bp2   = (const float*)d_in[11];
    const int*   ei    = (const int*)d_in[12];
    float* out = (float*)d_out;

    // CSR build
    k_zero<<<(NN + 255) / 256, 256>>>();
    k_deg<<<(EE + 255) / 256, 256>>>(ei);
    k_scanA<<<NB_SCAN, 256>>>();
    k_scanB<<<1, 512>>>();
    k_scanC<<<(NN + 255) / 256, 256>>>();
    k_fill<<<(EE + 255) / 256, 256>>>(ei);

    int ngrid = NN / NPB;          // 3125
    int ggrid = (NN + 15) / 16;    // 6250

    k_embed<<<ngrid, 128>>>(x, We, be, Wc1);
    k_gather<<<ggrid, 256>>>();
    k_mid<<<ngrid, 128>>>(bc1, Wc2);
    k_gather<<<ggrid, 256>>>();
    k_node_final<<<ngrid, 128>>>(bc2, Wp1);

    k_edge_out<<<EE / (16 * EPT), 256>>>(ei, eattr, Wp1, bp1, wp2, bp2, out);
}

// round 7
// speedup vs baseline: 2.0641x; 1.0136x over previous
#include <cuda_runtime.h>
#include <cuda_bf16.h>
#include <stdint.h>

#define NN 100000
#define EE 1600000
#define FN 32
#define FE 8
#define HH 64
#define NPB 32
#define NB_SCAN 391   // ceil(NN/256)

// ---------------- scratch (device globals) ------------------------------------
__device__ float g_g[NN * HH];    // g' = (h@W) * dinv[src-side]
__device__ float g_acc[NN * HH];  // aggregated (self + in-edges)
__device__ float g_a[NN * HH];
__device__ float g_b[NN * HH];
__device__ float g_dinv[NN];
__device__ int   g_degi[NN];
__device__ int   g_off[NN];
__device__ int   g_offtmp[NN];
__device__ int   g_cur[NN];
__device__ int   g_bsum[512];
__device__ int   g_csr[EE];       // src node of each in-edge, grouped by dst

// ---------------- degree / norm / CSR build -----------------------------------
__global__ void k_zero() {
    int n = blockIdx.x * blockDim.x + threadIdx.x;
    if (n < NN) g_degi[n] = 0;
}

__global__ void k_deg(const int* __restrict__ ei) {
    int e = blockIdx.x * blockDim.x + threadIdx.x;
    if (e < EE) atomicAdd(&g_degi[__ldg(&ei[EE + e])], 1);
}

// block-level inclusive scan (Hillis-Steele), emit exclusive + block sums
__global__ void k_scanA() {
    __shared__ int sm[256];
    int t = threadIdx.x;
    int idx = blockIdx.x * 256 + t;
    int v = (idx < NN) ? g_degi[idx] : 0;
    sm[t] = v;
    __syncthreads();
#pragma unroll
    for (int o = 1; o < 256; o <<= 1) {
        int x = (t >= o) ? sm[t - o] : 0;
        __syncthreads();
        sm[t] += x;
        __syncthreads();
    }
    if (idx < NN) g_offtmp[idx] = sm[t] - v;
    if (t == 255) g_bsum[blockIdx.x] = sm[255];
}

// merged: per-block prefix of block sums (by reduction) + offsets + dinv
__global__ void k_scanC() {
    __shared__ int sm[256];
    int t = threadIdx.x;
    int bid = blockIdx.x;
    int v = 0;
    if (t < bid) v += g_bsum[t];
    if (t + 256 < bid) v += g_bsum[t + 256];
    sm[t] = v;
    __syncthreads();
#pragma unroll
    for (int o = 128; o > 0; o >>= 1) {
        if (t < o) sm[t] += sm[t + o];
        __syncthreads();
    }
    int bbase = sm[0];
    int idx = bid * 256 + t;
    if (idx < NN) {
        int o = g_offtmp[idx] + bbase;
        g_off[idx] = o;
        g_cur[idx] = o;
        g_dinv[idx] = rsqrtf((float)(g_degi[idx] + 1));  // +1 self loop
    }
}

__global__ void k_fill(const int* __restrict__ ei) {
    int e = blockIdx.x * blockDim.x + threadIdx.x;
    if (e < EE) {
        int d = __ldg(&ei[EE + e]);
        int pos = atomicAdd(&g_cur[d], 1);
        g_csr[pos] = __ldg(&ei[e]);
    }
}

// float4 smem copy helper (stride = block threads)
__device__ __forceinline__ void cp4(float* dst, const float* src, int nfl,
                                    int tid, int nt) {
    const float4* s = (const float4*)src;
    float4* d = (float4*)dst;
    for (int i = tid; i < nfl / 4; i += nt) d[i] = s[i];
}

// ================== node GEMM kernels: 128 threads, 32 nodes/block ===========

// ---------------- K1: h0 = relu(x@We+be); g1' = (h0@Wc1)*dinv ----------------
__global__ __launch_bounds__(128) void k_embed(const float* __restrict__ x,
                                               const float* __restrict__ We,
                                               const float* __restrict__ be,
                                               const float* __restrict__ Wc1) {
    const int tid = threadIdx.x;
    const int j0 = (tid & 15) * 4;
    const int n0 = (tid >> 4) * 4;
    const int base = blockIdx.x * NPB;

    __shared__ float sWe[FN * HH];
    __shared__ float sWc[HH * HH];
    __shared__ float xs[NPB * FN];
    __shared__ float hs[NPB * HH];

    cp4(sWe, We, FN * HH, tid, 128);
    cp4(sWc, Wc1, HH * HH, tid, 128);
    cp4(xs, x + (long)base * FN, NPB * FN, tid, 128);
    __syncthreads();

    float a[4][4] = {};
#pragma unroll
    for (int mg = 0; mg < FN / 4; mg++) {
        float4 v[4];
#pragma unroll
        for (int r = 0; r < 4; r++) v[r] = *(const float4*)&xs[(n0 + r) * FN + mg * 4];
#pragma unroll
        for (int mm = 0; mm < 4; mm++) {
            float4 w = *(const float4*)&sWe[(mg * 4 + mm) * HH + j0];
#pragma unroll
            for (int r = 0; r < 4; r++) {
                float xv = ((const float*)&v[r])[mm];
                a[r][0] = fmaf(xv, w.x, a[r][0]);
                a[r][1] = fmaf(xv, w.y, a[r][1]);
                a[r][2] = fmaf(xv, w.z, a[r][2]);
                a[r][3] = fmaf(xv, w.w, a[r][3]);
            }
        }
    }
    {
        float4 bb = *(const float4*)&be[j0];
#pragma unroll
        for (int r = 0; r < 4; r++) {
            float4 h;
            h.x = fmaxf(a[r][0] + bb.x, 0.f);
            h.y = fmaxf(a[r][1] + bb.y, 0.f);
            h.z = fmaxf(a[r][2] + bb.z, 0.f);
            h.w = fmaxf(a[r][3] + bb.w, 0.f);
            *(float4*)&hs[(n0 + r) * HH + j0] = h;
        }
    }
    __syncthreads();

    float g[4][4] = {};
#pragma unroll
    for (int mg = 0; mg < HH / 4; mg++) {
        float4 v[4];
#pragma unroll
        for (int r = 0; r < 4; r++) v[r] = *(const float4*)&hs[(n0 + r) * HH + mg * 4];
#pragma unroll
        for (int mm = 0; mm < 4; mm++) {
            float4 w = *(const float4*)&sWc[(mg * 4 + mm) * HH + j0];
#pragma unroll
            for (int r = 0; r < 4; r++) {
                float xv = ((const float*)&v[r])[mm];
                g[r][0] = fmaf(xv, w.x, g[r][0]);
                g[r][1] = fmaf(xv, w.y, g[r][1]);
                g[r][2] = fmaf(xv, w.z, g[r][2]);
                g[r][3] = fmaf(xv, w.w, g[r][3]);
            }
        }
    }
#pragma unroll
    for (int r = 0; r < 4; r++) {
        float di = g_dinv[base + n0 + r];
        *(float4*)&g_g[(long)(base + n0 + r) * HH + j0] =
            make_float4(g[r][0] * di, g[r][1] * di, g[r][2] * di, g[r][3] * di);
    }
}

// ---------------- gather-aggregate: acc[n] = g'[n] + sum_{s->n} g'[s] --------
__global__ __launch_bounds__(256) void k_gather() {
    const int tid = threadIdx.x;
    const int p = tid & 15;
    const int grp = tid >> 4;
    const int n = blockIdx.x * 16 + grp;
    const unsigned hm = 0xFFFFu << (tid & 16);

    float4 acc = *(const float4*)&g_g[(long)n * HH + p * 4];  // self loop
    const int beg = g_off[n];
    const int end = beg + g_degi[n];

    for (int b = beg; b < end; b += 16) {
        int rem = end - b;
        int cnt = rem < 16 ? rem : 16;
        int myi = (p < cnt) ? __ldg(&g_csr[b + p]) : 0;
        for (int k = 0; k < cnt; k++) {
            int s = __shfl_sync(hm, myi, k, 16);
            float4 v = __ldg(reinterpret_cast<const float4*>(&g_g[(long)s * HH]) + p);
            acc.x += v.x; acc.y += v.y; acc.z += v.z; acc.w += v.w;
        }
    }
    *(float4*)&g_acc[(long)n * HH + p * 4] = acc;
}

// ---------------- K3: h1 = relu(acc*dinv + bc1); g2' = (h1@Wc2)*dinv ---------
__global__ __launch_bounds__(128) void k_mid(const float* __restrict__ bc,
                                             const float* __restrict__ Wc) {
    const int tid = threadIdx.x;
    const int j0 = (tid & 15) * 4;
    const int n0 = (tid >> 4) * 4;
    const int base = blockIdx.x * NPB;

    __shared__ float sWc[HH * HH];
    __shared__ float hs[NPB * HH];

    cp4(sWc, Wc, HH * HH, tid, 128);
    {
        const float4* acc4 = (const float4*)&g_acc[(long)base * HH];
        const float4* bc4 = (const float4*)bc;
        float4* hs4 = (float4*)hs;
        for (int i = tid; i < NPB * HH / 4; i += 128) {
            int row = i >> 4;
            float di = g_dinv[base + row];
            float4 v = acc4[i];
            float4 b = bc4[i & 15];
            v.x = fmaxf(fmaf(v.x, di, b.x), 0.f);
            v.y = fmaxf(fmaf(v.y, di, b.y), 0.f);
            v.z = fmaxf(fmaf(v.z, di, b.z), 0.f);
            v.w = fmaxf(fmaf(v.w, di, b.w), 0.f);
            hs4[i] = v;
        }
    }
    __syncthreads();

    float g[4][4] = {};
#pragma unroll
    for (int mg = 0; mg < HH / 4; mg++) {
        float4 v[4];
#pragma unroll
        for (int r = 0; r < 4; r++) v[r] = *(const float4*)&hs[(n0 + r) * HH + mg * 4];
#pragma unroll
        for (int mm = 0; mm < 4; mm++) {
            float4 w = *(const float4*)&sWc[(mg * 4 + mm) * HH + j0];
#pragma unroll
            for (int r = 0; r < 4; r++) {
                float xv = ((const float*)&v[r])[mm];
                g[r][0] = fmaf(xv, w.x, g[r][0]);
                g[r][1] = fmaf(xv, w.y, g[r][1]);
                g[r][2] = fmaf(xv, w.z, g[r][2]);
                g[r][3] = fmaf(xv, w.w, g[r][3]);
            }
        }
    }
#pragma unroll
    for (int r = 0; r < 4; r++) {
        float di = g_dinv[base + n0 + r];
        *(float4*)&g_g[(long)(base + n0 + r) * HH + j0] =
            make_float4(g[r][0] * di, g[r][1] * di, g[r][2] * di, g[r][3] * di);
    }
}

// ---------------- K5: h2 = relu(acc*dinv + bc2); a,b = h2 @ Wp1[0:128] -------
__global__ __launch_bounds__(128) void k_node_final(const float* __restrict__ bc2,
                                                    const float* __restrict__ Wp1) {
    const int tid = threadIdx.x;
    const int j0 = (tid & 15) * 4;
    const int n0 = (tid >> 4) * 4;
    const int base = blockIdx.x * NPB;

    __shared__ float sWa[HH * HH];
    __shared__ float sWb[HH * HH];
    __shared__ float hs[NPB * HH];

    cp4(sWa, Wp1, HH * HH, tid, 128);
    cp4(sWb, Wp1 + HH * HH, HH * HH, tid, 128);
    {
        const float4* acc4 = (const float4*)&g_acc[(long)base * HH];
        const float4* bc4 = (const float4*)bc2;
        float4* hs4 = (float4*)hs;
        for (int i = tid; i < NPB * HH / 4; i += 128) {
            int row = i >> 4;
            float di = g_dinv[base + row];
            float4 v = acc4[i];
            float4 b = bc4[i & 15];
            v.x = fmaxf(fmaf(v.x, di, b.x), 0.f);
            v.y = fmaxf(fmaf(v.y, di, b.y), 0.f);
            v.z = fmaxf(fmaf(v.z, di, b.z), 0.f);
            v.w = fmaxf(fmaf(v.w, di, b.w), 0.f);
            hs4[i] = v;
        }
    }
    __syncthreads();

    float A[4][4] = {};
    float B[4][4] = {};
#pragma unroll
    for (int mg = 0; mg < HH / 4; mg++) {
        float4 v[4];
#pragma unroll
        for (int r = 0; r < 4; r++) v[r] = *(const float4*)&hs[(n0 + r) * HH + mg * 4];
#pragma unroll
        for (int mm = 0; mm < 4; mm++) {
            int m = mg * 4 + mm;
            float4 wa = *(const float4*)&sWa[m * HH + j0];
            float4 wb = *(const float4*)&sWb[m * HH + j0];
#pragma unroll
            for (int r = 0; r < 4; r++) {
                float xv = ((const float*)&v[r])[mm];
                A[r][0] = fmaf(xv, wa.x, A[r][0]);
                A[r][1] = fmaf(xv, wa.y, A[r][1]);
                A[r][2] = fmaf(xv, wa.z, A[r][2]);
                A[r][3] = fmaf(xv, wa.w, A[r][3]);
                B[r][0] = fmaf(xv, wb.x, B[r][0]);
                B[r][1] = fmaf(xv, wb.y, B[r][1]);
                B[r][2] = fmaf(xv, wb.z, B[r][2]);
                B[r][3] = fmaf(xv, wb.w, B[r][3]);
            }
        }
    }
#pragma unroll
    for (int r = 0; r < 4; r++) {
        long rr = (long)(base + n0 + r) * HH + j0;
        *(float4*)&g_a[rr] = make_float4(A[r][0], A[r][1], A[r][2], A[r][3]);
        *(float4*)&g_b[rr] = make_float4(B[r][0], B[r][1], B[r][2], B[r][3]);
    }
}

// ---------------- K6: per-edge output, 4 edges per 16-thread group -----------
#define EPT 4
__global__ __launch_bounds__(256) void k_edge_out(const int* __restrict__ ei,
                           const float* __restrict__ eattr,
                           const float* __restrict__ Wp1,
                           const float* __restrict__ bp1,
                           const float* __restrict__ wp2,
                           const float* __restrict__ bp2,
                           float* __restrict__ out) {
    const int tid = threadIdx.x;
    const int p = tid & 15;
    const int grp = tid >> 4;
    const int j0 = p * 4;
    long e0 = ((long)blockIdx.x * 16 + grp) * EPT;

    float4 wt[FE];
#pragma unroll
    for (int k = 0; k < FE; k++)
        wt[k] = __ldg(reinterpret_cast<const float4*>(&Wp1[(2 * HH + k) * HH + j0]));
    float4 c0 = __ldg(reinterpret_cast<const float4*>(bp1) + p);
    float4 w2 = __ldg(reinterpret_cast<const float4*>(wp2) + p);
    float bias2 = __ldg(bp2);

    float res[EPT];
#pragma unroll
    for (int t = 0; t < EPT; t++) {
        long e = e0 + t;
        int s = __ldg(&ei[e]);
        int d = __ldg(&ei[EE + e]);
        float eav = (p < FE) ? __ldg(&eattr[e * FE + p]) : 0.0f;

        float4 av = __ldg(reinterpret_cast<const float4*>(&g_a[(long)s * HH]) + p);
        float4 bv = __ldg(reinterpret_cast<const float4*>(&g_b[(long)d * HH]) + p);

        float4 c = c0;
#pragma unroll
        for (int k = 0; k < FE; k++) {
            float ek = __shfl_sync(0xffffffffu, eav, k, 16);
            c.x = fmaf(ek, wt[k].x, c.x);
            c.y = fmaf(ek, wt[k].y, c.y);
            c.z = fmaf(ek, wt[k].z, c.z);
            c.w = fmaf(ek, wt[k].w, c.w);
        }

        float4 z;
        z.x = fmaxf(av.x + bv.x + c.x, 0.0f);
        z.y = fmaxf(av.y + bv.y + c.y, 0.0f);
        z.z = fmaxf(av.z + bv.z + c.z, 0.0f);
        z.w = fmaxf(av.w + bv.w + c.w, 0.0f);

        float part = z.x * w2.x + z.y * w2.y + z.z * w2.z + z.w * w2.w;
#pragma unroll
        for (int off = 8; off >= 1; off >>= 1)
            part += __shfl_down_sync(0xffffffffu, part, off, 16);

        res[t] = part + bias2;
    }
    if (p == 0)
        *reinterpret_cast<float4*>(&out[e0]) =
            make_float4(res[0], res[1], res[2], res[3]);
}

// ---------------- host launcher ----------------------------------------------
extern "C" void kernel_launch(void* const* d_in, const int* in_sizes, int n_in,
                              void* d_out, int out_size) {
    const float* x     = (const float*)d_in[0];
    const float* eattr = (const float*)d_in[1];
    const float* We    = (const float*)d_in[2];
    const float* be    = (const float*)d_in[3];
    const float* Wc1   = (const float*)d_in[4];
    const float* bc1   = (const float*)d_in[5];
    const float* Wc2   = (const float*)d_in[6];
    const float* bc2   = (const float*)d_in[7];
    const float* Wp1   = (const float*)d_in[8];
    const float* bp1   = (const float*)d_in[9];
    const float* wp2   = (const float*)d_in[10];
    const float* bp2   = (const float*)d_in[11];
    const int*   ei    = (const int*)d_in[12];
    float* out = (float*)d_out;

    // CSR build prologue (serial part: degrees -> offsets -> dinv)
    k_zero<<<(NN + 255) / 256, 256>>>();
    k_deg<<<(EE + 255) / 256, 256>>>(ei);
    k_scanA<<<NB_SCAN, 256>>>();
    k_scanC<<<NB_SCAN, 256>>>();

    int ngrid = NN / NPB;          // 3125
    int ggrid = (NN + 15) / 16;    // 6250

    // fork: k_fill (CSR population) runs concurrently with k_embed
    cudaStream_t s2;
    cudaStreamCreate(&s2);
    cudaEvent_t evFork, evJoin;
    cudaEventCreateWithFlags(&evFork, cudaEventDisableTiming);
    cudaEventCreateWithFlags(&evJoin, cudaEventDisableTiming);

    cudaEventRecord(evFork, 0);              // after scanC on legacy stream
    cudaStreamWaitEvent(s2, evFork, 0);
    k_fill<<<(EE + 255) / 256, 256, 0, s2>>>(ei);
    cudaEventRecord(evJoin, s2);

    k_embed<<<ngrid, 128>>>(x, We, be, Wc1); // legacy stream, concurrent

    cudaStreamWaitEvent(0, evJoin, 0);       // join before gather needs g_csr

    k_gather<<<ggrid, 256>>>();
    k_mid<<<ngrid, 128>>>(bc1, Wc2);
    k_gather<<<ggrid, 256>>>();
    k_node_final<<<ngrid, 128>>>(bc2, Wp1);

    k_edge_out<<<EE / (16 * EPT), 256>>>(ei, eattr, Wp1, bp1, wp2, bp2, out);

    cudaEventDestroy(evFork);
    cudaEventDestroy(evJoin);
    cudaStreamDestroy(s2);
}